// round 3
// baseline (speedup 1.0000x reference)
#include <cuda_runtime.h>
#include <cstdint>

// ============================================================
// Typed relational GCN on sm_103 baseline PTX (no tcgen05 — ptxas target
// is plain sm_103, so only baseline instructions: mma.sync, cp.async).
//
//   out = sum_k (adj==k) @ (V@w_k) + bias,  N=8192, F=256, fp32.
//
// Scheme: H_k quantized to s8 hi/lo (s = 8/127, s2 = s/256).
// Masks exact in s8. One int32 accumulator: pass0 accumulates
// sum mask*hi over all 3 types, acc <<= 8, pass1 adds sum mask*lo.
// out = s2 * acc + bias.  Predicted rel_err ~1.2e-4.
// ============================================================

#define NROWS 8192
#define FEAT  256
#define NCHUNKS 128          // K chunks of 64
#define STAGES 4
#define STAGE_BYTES (3 * 16 * 32 * 16)      // [type][ntile][lane][16B] = 24576
#define SMEM_TOTAL (STAGES * STAGE_BYTES)   // 98304

// B scratch, fragment-major:
// [chain(2)][type(3)][ntile(32)][kchunk(128)][lane(32)][16B] = 12.58 MB
__device__ __align__(256) uint8_t g_B[2u * 3u * 32u * 128u * 32u * 16u];

// ---------------- helpers ---------------------------------------------------

__device__ __forceinline__ uint32_t smem_u32(const void* p) {
    uint32_t a;
    asm("{ .reg .u64 t; cvta.to.shared.u64 t, %1; cvt.u32.u64 %0, t; }" : "=r"(a) : "l"(p));
    return a;
}

// pack low bytes of 4 int32 (values 0..3) into one 4-byte word
__device__ __forceinline__ uint32_t pack4(int4 v) {
    uint32_t a, b, r;
    asm("prmt.b32 %0, %1, %2, 0x40;"   : "=r"(a) : "r"(v.x), "r"(v.y));
    asm("prmt.b32 %0, %1, %2, 0x40;"   : "=r"(b) : "r"(v.z), "r"(v.w));
    asm("prmt.b32 %0, %1, %2, 0x5410;" : "=r"(r) : "r"(a), "r"(b));
    return r;
}

__device__ __forceinline__ void mma_s8(int* c,
                                       uint32_t a0, uint32_t a1, uint32_t a2, uint32_t a3,
                                       uint32_t b0, uint32_t b1) {
    asm volatile(
        "mma.sync.aligned.m16n8k32.row.col.s32.s8.s8.s32 "
        "{%0,%1,%2,%3}, {%4,%5,%6,%7}, {%8,%9}, {%0,%1,%2,%3};"
        : "+r"(c[0]), "+r"(c[1]), "+r"(c[2]), "+r"(c[3])
        : "r"(a0), "r"(a1), "r"(a2), "r"(a3), "r"(b0), "r"(b1));
}

__device__ __forceinline__ void cp_async16(uint32_t smem_addr, const void* gptr) {
    asm volatile("cp.async.cg.shared.global [%0], [%1], 16;"
                 :: "r"(smem_addr), "l"(gptr) : "memory");
}
#define CP_COMMIT() asm volatile("cp.async.commit_group;" ::: "memory")
#define CP_WAIT3()  asm volatile("cp.async.wait_group 3;" ::: "memory")
#define CP_WAIT0()  asm volatile("cp.async.wait_group 0;" ::: "memory")

// ---------------- Stage 1: H_k = V @ w_k -> s8 hi/lo fragment-major ---------
// grid (128 j-tiles, 4 n-tiles, 3 types), block (16,16)

__global__ void stage1_kernel(const float* __restrict__ V,
                              const float* __restrict__ w1,
                              const float* __restrict__ w2,
                              const float* __restrict__ w3) {
    const int j0 = blockIdx.x * 64;        // K (row) offset of H tile
    const int n0 = blockIdx.y * 64;        // feature offset
    const int type = blockIdx.z;
    const float* w = (type == 0) ? w1 : (type == 1) ? w2 : w3;

    __shared__ float Vs[16][68];
    __shared__ float Ws[16][68];
    __shared__ float Ts[64][65];           // [n][j]

    const int tx = threadIdx.x, ty = threadIdx.y;
    const int t = ty * 16 + tx;

    float acc[4][4];
#pragma unroll
    for (int i = 0; i < 4; i++)
#pragma unroll
        for (int j = 0; j < 4; j++) acc[i][j] = 0.f;

    const int vrow = t >> 2, vci = (t & 3) * 4;
    const int wc = t >> 4, wn = (t & 15) * 4;

    for (int ks = 0; ks < 16; ks++) {
        float4 v = *(const float4*)&V[(size_t)(j0 + vrow) * 256 + ks * 16 + vci];
        Vs[vci + 0][vrow] = v.x; Vs[vci + 1][vrow] = v.y;
        Vs[vci + 2][vrow] = v.z; Vs[vci + 3][vrow] = v.w;
        *(float4*)&Ws[wc][wn] = *(const float4*)&w[(size_t)(ks * 16 + wc) * 256 + n0 + wn];
        __syncthreads();
#pragma unroll
        for (int c = 0; c < 16; c++) {
            float4 rv = *(const float4*)&Vs[c][ty * 4];
            float4 rw = *(const float4*)&Ws[c][tx * 4];
            float a[4] = {rv.x, rv.y, rv.z, rv.w};
            float b[4] = {rw.x, rw.y, rw.z, rw.w};
#pragma unroll
            for (int i = 0; i < 4; i++)
#pragma unroll
                for (int j = 0; j < 4; j++) acc[i][j] += a[i] * b[j];
        }
        __syncthreads();
    }
#pragma unroll
    for (int i = 0; i < 4; i++)
#pragma unroll
        for (int j = 0; j < 4; j++) Ts[tx * 4 + j][ty * 4 + i] = acc[i][j];
    __syncthreads();

    // quantize + write fragment-major
    const int nl = t >> 2;                 // 0..63
    const int jbl = (t & 3) * 16;          // 0,16,32,48
    const int n = n0 + nl;
    const int kchunk = blockIdx.x;         // (j0+jbl)>>6 == blockIdx.x
    const int g = jbl >> 4;                // byte-group 0..3
    const int ntile = n >> 3;
    const int lane_base = (n & 7) << 2;

    const float s = 8.0f / 127.0f;
    const float inv_s = 127.0f / 8.0f;
    const float inv_s2 = 127.0f * 256.0f / 8.0f;

    uint32_t whi[4], wlo[4];
#pragma unroll
    for (int q = 0; q < 4; q++) {
        uint32_t h = 0, lo = 0;
#pragma unroll
        for (int b = 0; b < 4; b++) {
            float x = Ts[nl][jbl + q * 4 + b];
            int hi = __float2int_rn(x * inv_s);
            hi = max(-127, min(127, hi));
            float r = x - (float)hi * s;
            int l2 = __float2int_rn(r * inv_s2);
            l2 = max(-127, min(127, l2));
            h  |= (uint32_t)(hi & 0xFF) << (8 * b);
            lo |= (uint32_t)(l2 & 0xFF) << (8 * b);
        }
        whi[q] = h; wlo[q] = lo;
    }

    size_t base_hi = ((((size_t)(0 * 3 + type) * 32 + ntile) * 128 + kchunk) * 32) * 16;
    size_t base_lo = ((((size_t)(1 * 3 + type) * 32 + ntile) * 128 + kchunk) * 32) * 16;
#pragma unroll
    for (int q = 0; q < 4; q++) {
        *(uint32_t*)&g_B[base_hi + (size_t)(lane_base + q) * 16 + g * 4] = whi[q];
        *(uint32_t*)&g_B[base_lo + (size_t)(lane_base + q) * 16 + g * 4] = wlo[q];
    }
}

// ---------------- Stage 2: mask-GEMM on mma.sync s8 -------------------------
// grid 128: bid -> (m_tile = bid>>1, n_half = bid&1). 256 threads, 8 warps.
// Warp wid owns rows [i0 + wid*16, +16). CTA covers 128 output features.

__global__ void __launch_bounds__(256, 1)
stage2_kernel(const int* __restrict__ adj,
              const float* __restrict__ bias,
              float* __restrict__ out) {
    extern __shared__ uint8_t smem[];
    const uint32_t smem_base = smem_u32(smem);

    const int tid = threadIdx.x;
    const int wid = tid >> 5, l = tid & 31;
    const int m_tile = blockIdx.x >> 1;
    const int n_half = blockIdx.x & 1;
    const int i0 = m_tile * 128;
    const int n0 = n_half * 128;

    const int row = i0 + wid * 16 + (l >> 2);
    const int4* adjA = (const int4*)(adj + (size_t)row * NROWS);
    const int4* adjB = (const int4*)(adj + (size_t)(row + 8) * NROWS);

    int acc[16][4];
#pragma unroll
    for (int nt = 0; nt < 16; nt++)
#pragma unroll
        for (int r = 0; r < 4; r++) acc[nt][r] = 0;

    for (int chain = 0; chain < 2; chain++) {
        const uint8_t* gsrc = g_B + (size_t)chain * (3u * 32u * 128u * 32u * 16u);

        // prologue: stage chunks 0..STAGES-2
#pragma unroll
        for (int p = 0; p < STAGES - 1; p++) {
#pragma unroll
            for (int q = 0; q < 6; q++) {
                int idx = tid + 256 * q;                 // 0..1535
                int type = idx >> 9;
                int rem = idx & 511;
                int nt = rem >> 5;
                int lane = rem & 31;
                const uint8_t* src = gsrc +
                    ((((size_t)type * 32 + n_half * 16 + nt) * 128 + p) * 32 + lane) * 16;
                cp_async16(smem_base + (p & 3) * STAGE_BYTES + idx * 16, src);
            }
            CP_COMMIT();
        }

        // preload adj chunk 0
        int4 ar[8];
#pragma unroll
        for (int q = 0; q < 4; q++) {
            ar[q]     = adjA[(l & 3) + 4 * q];
            ar[4 + q] = adjB[(l & 3) + 4 * q];
        }

        for (int c = 0; c < NCHUNKS; c++) {
            __syncthreads();   // prior iteration's consumers done -> buffer reusable
            if (c + STAGES - 1 < NCHUNKS) {
                const int p = c + STAGES - 1;
#pragma unroll
                for (int q = 0; q < 6; q++) {
                    int idx = tid + 256 * q;
                    int type = idx >> 9;
                    int rem = idx & 511;
                    int nt = rem >> 5;
                    int lane = rem & 31;
                    const uint8_t* src = gsrc +
                        ((((size_t)type * 32 + n_half * 16 + nt) * 128 + p) * 32 + lane) * 16;
                    cp_async16(smem_base + (p & 3) * STAGE_BYTES + idx * 16, src);
                }
            }
            CP_COMMIT();

            // pack current adj into byte words
            uint32_t pk[8];
#pragma unroll
            for (int q = 0; q < 8; q++) pk[q] = pack4(ar[q]);

            // prefetch adj for next chunk (latency hidden by this chunk's mma)
            if (c + 1 < NCHUNKS) {
#pragma unroll
                for (int q = 0; q < 4; q++) {
                    ar[q]     = adjA[(c + 1) * 16 + (l & 3) + 4 * q];
                    ar[4 + q] = adjB[(c + 1) * 16 + (l & 3) + 4 * q];
                }
            }

            CP_WAIT3();
            __syncthreads();   // chunk c staged & visible

            const uint8_t* sb = smem + (c & 3) * STAGE_BYTES;
#pragma unroll
            for (int t = 0; t < 3; t++) {
                const uint32_t cmp = 0x01010101u * (t + 1);
                uint32_t m[8];
#pragma unroll
                for (int q = 0; q < 8; q++)
                    m[q] = __vcmpeq4(pk[q], cmp) & 0x01010101u;
#pragma unroll
                for (int nt = 0; nt < 16; nt++) {
                    uint4 bf = *(const uint4*)(sb + (((t * 16 + nt) * 32) + l) * 16);
                    // k-step 0: k 0..31 of chunk
                    mma_s8(acc[nt], m[0], m[4], m[1], m[5], bf.x, bf.y);
                    // k-step 1: k 32..63
                    mma_s8(acc[nt], m[2], m[6], m[3], m[7], bf.z, bf.w);
                }
            }
        }

        CP_WAIT0();
        __syncthreads();

        if (chain == 0) {
#pragma unroll
            for (int nt = 0; nt < 16; nt++)
#pragma unroll
                for (int r = 0; r < 4; r++) acc[nt][r] <<= 8;   // acc = 256*S_hi
        }
    }

    // epilogue: out = s2 * acc + bias
    const float s2 = 8.0f / (127.0f * 256.0f);
#pragma unroll
    for (int nt = 0; nt < 16; nt++) {
        int col = n0 + nt * 8 + 2 * (l & 3);
        float b0 = __ldg(&bias[col]);
        float b1 = __ldg(&bias[col + 1]);
        float2 r0 = make_float2(s2 * (float)acc[nt][0] + b0,
                                s2 * (float)acc[nt][1] + b1);
        float2 r1 = make_float2(s2 * (float)acc[nt][2] + b0,
                                s2 * (float)acc[nt][3] + b1);
        *(float2*)&out[(size_t)row * FEAT + col] = r0;
        *(float2*)&out[(size_t)(row + 8) * FEAT + col] = r1;
    }
}

// ---------------- launch ---------------------------------------------------

extern "C" void kernel_launch(void* const* d_in, const int* in_sizes, int n_in,
                              void* d_out, int out_size) {
    const float* V    = (const float*)d_in[0];
    const int*   adj  = (const int*)d_in[1];
    const float* w1   = (const float*)d_in[2];
    const float* w2   = (const float*)d_in[3];
    const float* w3   = (const float*)d_in[4];
    const float* bias = (const float*)d_in[5];
    float* out = (float*)d_out;

    cudaFuncSetAttribute(stage2_kernel,
                         cudaFuncAttributeMaxDynamicSharedMemorySize, SMEM_TOTAL);

    stage1_kernel<<<dim3(128, 4, 3), dim3(16, 16)>>>(V, w1, w2, w3);
    stage2_kernel<<<128, 256, SMEM_TOTAL>>>(adj, bias, out);
}

// round 4
// speedup vs baseline: 3.8185x; 3.8185x over previous
#include <cuda_runtime.h>
#include <cuda_fp16.h>
#include <cstdint>

// ============================================================
// Typed relational GCN, sm_103 baseline PTX (no tcgen05 allowed).
//   out = sum_k (adj==k) @ (V@w_k) + bias,  N=8192, F=256, fp32.
//
// R3: single fp16 chain on mma.sync.m16n8k16.f32.f16.f16.f32.
// Masks (0/1) exact in fp16; H_k quantized to fp16 (rel ~2.8e-4).
// Same legacy-MMA instruction count as the s8 hi/lo version but
// half the MAC volume -> tests per-instr vs per-MAC cost model.
// ============================================================

#define NROWS 8192
#define FEAT  256
#define NCHUNKS 128                           // K chunks of 64
#define STAGES 4
#define STAGE_BYTES (3 * 16 * 2 * 32 * 16)    // [type][nt][half][lane][16B] = 49152
#define SMEM_TOTAL (STAGES * STAGE_BYTES)     // 196608

// B scratch, fragment-major fp16:
// [type(3)][ntile(32)][kchunk(128)][half(2)][lane(32)][16B] = 12.58 MB
__device__ __align__(256) uint8_t g_B[3u * 32u * 128u * 2u * 32u * 16u];

// ---------------- helpers ---------------------------------------------------

__device__ __forceinline__ uint32_t smem_u32(const void* p) {
    uint32_t a;
    asm("{ .reg .u64 t; cvta.to.shared.u64 t, %1; cvt.u32.u64 %0, t; }" : "=r"(a) : "l"(p));
    return a;
}

// pack low bytes of 4 int32 (values 0..3) into one 4-byte word
__device__ __forceinline__ uint32_t pack4(int a, int b, int c, int d) {
    uint32_t x, y, r;
    asm("prmt.b32 %0, %1, %2, 0x40;"   : "=r"(x) : "r"(a), "r"(b));
    asm("prmt.b32 %0, %1, %2, 0x40;"   : "=r"(y) : "r"(c), "r"(d));
    asm("prmt.b32 %0, %1, %2, 0x5410;" : "=r"(r) : "r"(x), "r"(y));
    return r;
}

__device__ __forceinline__ void mma_f16(float* c,
                                        uint32_t a0, uint32_t a1, uint32_t a2, uint32_t a3,
                                        uint32_t b0, uint32_t b1) {
    asm volatile(
        "mma.sync.aligned.m16n8k16.row.col.f32.f16.f16.f32 "
        "{%0,%1,%2,%3}, {%4,%5,%6,%7}, {%8,%9}, {%0,%1,%2,%3};"
        : "+f"(c[0]), "+f"(c[1]), "+f"(c[2]), "+f"(c[3])
        : "r"(a0), "r"(a1), "r"(a2), "r"(a3), "r"(b0), "r"(b1));
}

__device__ __forceinline__ void cp_async16(uint32_t smem_addr, const void* gptr) {
    asm volatile("cp.async.cg.shared.global [%0], [%1], 16;"
                 :: "r"(smem_addr), "l"(gptr) : "memory");
}
#define CP_COMMIT() asm volatile("cp.async.commit_group;" ::: "memory")
#define CP_WAIT3()  asm volatile("cp.async.wait_group 3;" ::: "memory")
#define CP_WAIT0()  asm volatile("cp.async.wait_group 0;" ::: "memory")

// ---------------- Stage 1: H_k = V @ w_k -> fp16 fragment-major -------------
// grid (128 j-tiles, 4 n-tiles, 3 types), block (16,16). FFMA-roofline bound.

__global__ void stage1_kernel(const float* __restrict__ V,
                              const float* __restrict__ w1,
                              const float* __restrict__ w2,
                              const float* __restrict__ w3) {
    const int j0 = blockIdx.x * 64;        // K (row) offset of H tile
    const int n0 = blockIdx.y * 64;        // feature offset
    const int type = blockIdx.z;
    const float* w = (type == 0) ? w1 : (type == 1) ? w2 : w3;

    __shared__ float Vs[16][68];
    __shared__ float Ws[16][68];
    __shared__ float Ts[64][65];           // [n][j]

    const int tx = threadIdx.x, ty = threadIdx.y;
    const int t = ty * 16 + tx;

    float acc[4][4];
#pragma unroll
    for (int i = 0; i < 4; i++)
#pragma unroll
        for (int j = 0; j < 4; j++) acc[i][j] = 0.f;

    const int vrow = t >> 2, vci = (t & 3) * 4;
    const int wc = t >> 4, wn = (t & 15) * 4;

    for (int ks = 0; ks < 16; ks++) {
        float4 v = *(const float4*)&V[(size_t)(j0 + vrow) * 256 + ks * 16 + vci];
        Vs[vci + 0][vrow] = v.x; Vs[vci + 1][vrow] = v.y;
        Vs[vci + 2][vrow] = v.z; Vs[vci + 3][vrow] = v.w;
        *(float4*)&Ws[wc][wn] = *(const float4*)&w[(size_t)(ks * 16 + wc) * 256 + n0 + wn];
        __syncthreads();
#pragma unroll
        for (int c = 0; c < 16; c++) {
            float4 rv = *(const float4*)&Vs[c][ty * 4];
            float4 rw = *(const float4*)&Ws[c][tx * 4];
            float a[4] = {rv.x, rv.y, rv.z, rv.w};
            float b[4] = {rw.x, rw.y, rw.z, rw.w};
#pragma unroll
            for (int i = 0; i < 4; i++)
#pragma unroll
                for (int j = 0; j < 4; j++) acc[i][j] += a[i] * b[j];
        }
        __syncthreads();
    }
#pragma unroll
    for (int i = 0; i < 4; i++)
#pragma unroll
        for (int j = 0; j < 4; j++) Ts[tx * 4 + j][ty * 4 + i] = acc[i][j];
    __syncthreads();

    // fragment-major fp16 write.
    // thread t owns n = n0 + (t>>2), kstep s = t&3 (j-range 16s..16s+15 of chunk)
    const int nl = t >> 2;
    const int s = t & 3;
    const int jb = s * 16;
    const int n = n0 + nl;
    const int nt = n >> 3;
    const int kc = blockIdx.x;

#pragma unroll
    for (int c = 0; c < 4; c++) {
        __half2 p01 = __floats2half2_rn(Ts[nl][jb + 2 * c], Ts[nl][jb + 2 * c + 1]);
        __half2 p89 = __floats2half2_rn(Ts[nl][jb + 2 * c + 8], Ts[nl][jb + 2 * c + 9]);
        uint2 val = make_uint2(*reinterpret_cast<uint32_t*>(&p01),
                               *reinterpret_cast<uint32_t*>(&p89));
        const int lane = 4 * (n & 7) + c;
        size_t off = (((((size_t)(type * 32 + nt) * 128 + kc) * 2 + (s >> 1)) * 32 + lane)) * 16
                   + (size_t)(s & 1) * 8;
        *(uint2*)&g_B[off] = val;
    }
}

// ---------------- Stage 2: mask-GEMM on mma.sync f16 ------------------------
// grid 128: bid -> (m_tile = bid>>1, n_half = bid&1). 256 threads, 8 warps.
// Warp wid owns rows [i0 + wid*16, +16). CTA covers 128 output features.

__global__ void __launch_bounds__(256, 1)
stage2_kernel(const int* __restrict__ adj,
              const float* __restrict__ bias,
              float* __restrict__ out) {
    extern __shared__ uint8_t smem[];
    const uint32_t smem_base = smem_u32(smem);

    const int tid = threadIdx.x;
    const int wid = tid >> 5, l = tid & 31;
    const int m_tile = blockIdx.x >> 1;
    const int n_half = blockIdx.x & 1;
    const int i0 = m_tile * 128;
    const int n0 = n_half * 128;

    const int rowA = i0 + wid * 16 + (l >> 2);
    const int2* aA = (const int2*)(adj + (size_t)rowA * NROWS);
    const int2* aB = (const int2*)(adj + (size_t)(rowA + 8) * NROWS);
    const int li = l & 3;

    float acc[16][4];
#pragma unroll
    for (int nt = 0; nt < 16; nt++)
#pragma unroll
        for (int r = 0; r < 4; r++) acc[nt][r] = 0.f;

    // prologue: stage chunks 0..STAGES-2
#pragma unroll
    for (int p = 0; p < STAGES - 1; p++) {
#pragma unroll
        for (int q = 0; q < 12; q++) {
            int idx = tid + 256 * q;                 // 0..3071
            int type = idx >> 10;
            int rem = idx & 1023;
            int nt = rem >> 6;
            int hl = (rem >> 5) & 1;
            int lane = rem & 31;
            const uint8_t* src = g_B +
                (((((size_t)(type * 32 + n_half * 16 + nt) * 128 + p) * 2 + hl) * 32 + lane)) * 16;
            cp_async16(smem_base + p * STAGE_BYTES + idx * 16, src);
        }
        CP_COMMIT();
    }

    // preload adj chunk 0: int2 at idx = chunk*32 + 8s + li (+4 for k+8 group)
    int2 vA0[4], vA1[4], vB0[4], vB1[4];
#pragma unroll
    for (int s = 0; s < 4; s++) {
        vA0[s] = aA[8 * s + li];
        vA1[s] = aA[8 * s + li + 4];
        vB0[s] = aB[8 * s + li];
        vB1[s] = aB[8 * s + li + 4];
    }

    for (int c = 0; c < NCHUNKS; c++) {
        __syncthreads();   // all warps done consuming the buffer being overwritten
        if (c + STAGES - 1 < NCHUNKS) {
            const int p = c + STAGES - 1;
#pragma unroll
            for (int q = 0; q < 12; q++) {
                int idx = tid + 256 * q;
                int type = idx >> 10;
                int rem = idx & 1023;
                int nt = rem >> 6;
                int hl = (rem >> 5) & 1;
                int lane = rem & 31;
                const uint8_t* src = g_B +
                    (((((size_t)(type * 32 + n_half * 16 + nt) * 128 + p) * 2 + hl) * 32 + lane)) * 16;
                cp_async16(smem_base + (p & 3) * STAGE_BYTES + idx * 16, src);
            }
        }
        CP_COMMIT();

        // pack current adj: pkA[s] bytes = [A[r][16s+2c], A[r][16s+2c+1],
        //                                   A[r][16s+2c+8], A[r][16s+2c+9]]
        uint32_t pkA[4], pkB[4];
#pragma unroll
        for (int s = 0; s < 4; s++) {
            pkA[s] = pack4(vA0[s].x, vA0[s].y, vA1[s].x, vA1[s].y);
            pkB[s] = pack4(vB0[s].x, vB0[s].y, vB1[s].x, vB1[s].y);
        }

        // prefetch adj for next chunk (hidden under this chunk's mma)
        if (c + 1 < NCHUNKS) {
            const int base = (c + 1) * 32;
#pragma unroll
            for (int s = 0; s < 4; s++) {
                vA0[s] = aA[base + 8 * s + li];
                vA1[s] = aA[base + 8 * s + li + 4];
                vB0[s] = aB[base + 8 * s + li];
                vB1[s] = aB[base + 8 * s + li + 4];
            }
        }

        CP_WAIT3();
        __syncthreads();   // chunk c fully staged & visible to all warps

        const uint32_t sb = smem_base + (c & 3) * STAGE_BYTES;
#pragma unroll
        for (int t = 0; t < 3; t++) {
            const uint32_t cmp = 0x01010101u * (t + 1);
            // build fp16 one-hot A-fragments for all 4 ksteps
            uint32_t am[4][4];
#pragma unroll
            for (int s = 0; s < 4; s++) {
                uint32_t eA = __vcmpeq4(pkA[s], cmp) & 0x01010101u;
                uint32_t eB = __vcmpeq4(pkB[s], cmp) & 0x01010101u;
                am[s][0] = (eA & 1u) * 0x3C00u + (eA & 0x100u) * 0x3C0000u;          // rowA, k lo
                am[s][1] = (eB & 1u) * 0x3C00u + (eB & 0x100u) * 0x3C0000u;          // rowB, k lo
                am[s][2] = ((eA >> 16) & 1u) * 0x3C00u + ((eA >> 16) & 0x100u) * 0x3C0000u; // rowA, k+8
                am[s][3] = ((eB >> 16) & 1u) * 0x3C00u + ((eB >> 16) & 0x100u) * 0x3C0000u; // rowB, k+8
            }
#pragma unroll
            for (int nt = 0; nt < 16; nt++) {
                const uint32_t base = sb + (uint32_t)(((t * 16 + nt) * 2) * 512 + l * 16);
                uint4 u0, u1;
                asm volatile("ld.shared.v4.u32 {%0,%1,%2,%3}, [%4];"
                             : "=r"(u0.x), "=r"(u0.y), "=r"(u0.z), "=r"(u0.w) : "r"(base));
                asm volatile("ld.shared.v4.u32 {%0,%1,%2,%3}, [%4];"
                             : "=r"(u1.x), "=r"(u1.y), "=r"(u1.z), "=r"(u1.w) : "r"(base + 512));
                mma_f16(acc[nt], am[0][0], am[0][1], am[0][2], am[0][3], u0.x, u0.y);
                mma_f16(acc[nt], am[1][0], am[1][1], am[1][2], am[1][3], u0.z, u0.w);
                mma_f16(acc[nt], am[2][0], am[2][1], am[2][2], am[2][3], u1.x, u1.y);
                mma_f16(acc[nt], am[3][0], am[3][1], am[3][2], am[3][3], u1.z, u1.w);
            }
        }
    }

    CP_WAIT0();

    // epilogue: out = acc + bias
#pragma unroll
    for (int nt = 0; nt < 16; nt++) {
        int col = n0 + nt * 8 + 2 * (l & 3);
        float b0 = __ldg(&bias[col]);
        float b1 = __ldg(&bias[col + 1]);
        float2 r0 = make_float2(acc[nt][0] + b0, acc[nt][1] + b1);
        float2 r1 = make_float2(acc[nt][2] + b0, acc[nt][3] + b1);
        *(float2*)&out[(size_t)rowA * FEAT + col] = r0;
        *(float2*)&out[(size_t)(rowA + 8) * FEAT + col] = r1;
    }
}

// ---------------- launch ---------------------------------------------------

extern "C" void kernel_launch(void* const* d_in, const int* in_sizes, int n_in,
                              void* d_out, int out_size) {
    const float* V    = (const float*)d_in[0];
    const int*   adj  = (const int*)d_in[1];
    const float* w1   = (const float*)d_in[2];
    const float* w2   = (const float*)d_in[3];
    const float* w3   = (const float*)d_in[4];
    const float* bias = (const float*)d_in[5];
    float* out = (float*)d_out;

    cudaFuncSetAttribute(stage2_kernel,
                         cudaFuncAttributeMaxDynamicSharedMemorySize, SMEM_TOTAL);

    stage1_kernel<<<dim3(128, 4, 3), dim3(16, 16)>>>(V, w1, w2, w3);
    stage2_kernel<<<128, 256, SMEM_TOTAL>>>(adj, bias, out);
}